// round 14
// baseline (speedup 1.0000x reference)
#include <cuda_runtime.h>
#include <math.h>

#define NN 100000
#define EE 1600000
#define HH 128
#define CC 64
#define KK 10

typedef unsigned long long u64;
typedef long long s64;

#define LN_SCALE   16777216.0        /* 2^24 */
#define LN_INVSCALE 5.9604644775390625e-8f

// ---------------- device scratch (allocation-free workaround) ----------------
__device__ __align__(16) float g_featA[NN * HH];
__device__ __align__(16) float g_featB[NN * HH];
__device__ int   g_deg[NN];
__device__ float g_norm[NN];
__device__ float g_invdeg[NN];
__device__ int   g_scan[NN];
__device__ int   g_bsum[128];
__device__ int   g_rowstart[NN + 1];
__device__ int   g_rowcur[NN];
__device__ int   g_csr[EE];
__device__ int   g_pred[NN];
__device__ float g_f1[NN];
__device__ float g_f2[NN];
__device__ s64   g_lnacc[2][4];   // parity-double-buffered scaled-int LN sums

// ---------------- packed fp32x2 helpers ----------------
__device__ __forceinline__ u64 ffma2(u64 a, u64 b, u64 c) {
    u64 d;
    asm("fma.rn.f32x2 %0, %1, %2, %3;" : "=l"(d) : "l"(a), "l"(b), "l"(c));
    return d;
}
__device__ __forceinline__ u64 pk(float x, float y) {
    u64 d;
    asm("mov.b64 %0, {%1, %2};" : "=l"(d) : "f"(x), "f"(y));
    return d;
}
__device__ __forceinline__ float2 upk(u64 v) {
    float2 r;
    asm("mov.b64 {%0, %1}, %2;" : "=f"(r.x), "=f"(r.y) : "l"(v));
    return r;
}

// ---------------- setup kernels ----------------
__global__ void k_zero() {
    int i = blockIdx.x * blockDim.x + threadIdx.x;
    if (i < NN) { g_deg[i] = 0; g_rowcur[i] = 0; }
    if (i < 8) ((s64*)g_lnacc)[i] = 0ll;
}

__global__ void k_deg(const int* __restrict__ dst) {
    int e = blockIdx.x * blockDim.x + threadIdx.x;
    if (e < EE) atomicAdd(&g_deg[dst[e]], 1);
}

__global__ void k_norm() {
    int i = blockIdx.x * blockDim.x + threadIdx.x;
    if (i < NN) {
        int d = g_deg[i];
        float dc = (d > 0) ? (float)d : 1.0f;
        g_norm[i] = rsqrtf(dc);
        g_invdeg[i] = 1.0f / dc;
    }
}

// inclusive scan within 1024-element blocks
__global__ void k_scan1() {
    __shared__ int sh[1024];
    int tid = threadIdx.x;
    int i = blockIdx.x * 1024 + tid;
    int v = (i < NN) ? g_deg[i] : 0;
    sh[tid] = v;
    __syncthreads();
    for (int off = 1; off < 1024; off <<= 1) {
        int t = (tid >= off) ? sh[tid - off] : 0;
        __syncthreads();
        sh[tid] += t;
        __syncthreads();
    }
    if (i < NN) g_scan[i] = sh[tid];
    if (tid == 1023) g_bsum[blockIdx.x] = sh[1023];
}

__global__ void k_scan2(int nb) {
    int run = 0;
    for (int b = 0; b < nb; b++) { int t = g_bsum[b]; g_bsum[b] = run; run += t; }
}

__global__ void k_scan3() {
    int i = blockIdx.x * blockDim.x + threadIdx.x;
    if (i < NN) g_rowstart[i] = g_scan[i] - g_deg[i] + g_bsum[i >> 10];
    if (i == 0) g_rowstart[NN] = EE;
}

__global__ void k_csrfill(const int* __restrict__ src, const int* __restrict__ dst) {
    int e = blockIdx.x * blockDim.x + threadIdx.x;
    if (e < EE) {
        int d = dst[e];
        int pos = g_rowstart[d] + atomicAdd(&g_rowcur[d], 1);
        g_csr[pos] = src[e];
    }
}

// feat buffer initialized to pre-scaled feat: Fs(0) = feat_in * norm
__global__ void k_init(const float* __restrict__ fin) {
    int i = blockIdx.x * blockDim.x + threadIdx.x;
    if (i < NN * (HH / 4)) {
        int n = i >> 5;
        float nm = g_norm[n];
        float4 v = ((const float4*)fin)[i];
        v.x *= nm; v.y *= nm; v.z *= nm; v.w *= nm;
        ((float4*)g_featA)[i] = v;
    }
}

// ---------------- per-iteration kernels ----------------

// before iteration 0: argmax over the input logits -> pred(0)
__global__ void k_argmax0(const float* __restrict__ logits) {
    int n = (blockIdx.x * blockDim.x + threadIdx.x) >> 5;
    int lane = threadIdx.x & 31;
    if (n >= NN) return;
    const float* row = logits + (size_t)n * CC;
    float v0 = row[lane], v1 = row[lane + 32];
    float bv; int bc;
    if (v1 > v0) { bv = v1; bc = lane + 32; } else { bv = v0; bc = lane; }
    #pragma unroll
    for (int off = 16; off; off >>= 1) {
        float ov = __shfl_down_sync(0xffffffffu, bv, off);
        int   oc = __shfl_down_sync(0xffffffffu, bc, off);
        if (ov > bv || (ov == bv && oc < bc)) { bv = ov; bc = oc; }
    }
    if (lane == 0) g_pred[n] = bc;
}

// neighborhood stats for iteration i: f1/f2 from pred(i), LN partials into
// g_lnacc[par] (scaled-int64 atomics: bit-exact, order-independent).
__global__ void k_stats(int par) {
    __shared__ int hist[32][CC];
    __shared__ float4 red[32];
    int tid = threadIdx.x, w = tid >> 5, lane = tid & 31;
    int n = blockIdx.x * 32 + w;
    hist[w][lane] = 0; hist[w][lane + 32] = 0;
    __syncwarp();
    int pd = g_pred[n];
    int rs = g_rowstart[n], re = g_rowstart[n + 1];
    int eq = 0;
    for (int idx = rs + lane; idx < re; idx += 32) {
        int ps = g_pred[g_csr[idx]];
        eq += (ps == pd);
        atomicAdd(&hist[w][ps], 1);
    }
    __syncwarp();
    #pragma unroll
    for (int off = 16; off; off >>= 1) eq += __shfl_down_sync(0xffffffffu, eq, off);
    float inv = g_invdeg[n];
    float p0 = fmaxf((float)hist[w][lane] * inv, 1e-5f);
    float p1 = fmaxf((float)hist[w][lane + 32] * inv, 1e-5f);
    float ent = -(p0 * logf(p0) + p1 * logf(p1));
    #pragma unroll
    for (int off = 16; off; off >>= 1) ent += __shfl_down_sync(0xffffffffu, ent, off);
    if (lane == 0) {
        float f1 = (float)eq * inv;
        g_f1[n] = f1; g_f2[n] = ent;
        red[w] = make_float4(f1, f1 * f1, ent, ent * ent);
    }
    __syncthreads();
    if (tid < 4) {
        float s = 0.0f;
        #pragma unroll
        for (int ww = 0; ww < 32; ww++) s += ((const float*)&red[ww])[tid];
        s64 q = __double2ll_rn((double)s * LN_SCALE);
        atomicAdd((u64*)&g_lnacc[par][tid], (u64)q);
    }
}

// FUSED spmm + gemm + argmax for iteration i:
//   gather agg over neighbors, gate with LN(par), combine -> feat(i+1) row
//   (held in registers), store it, then compute logits(i+1) = row @ W + b and
//   pred(i+1) WITHOUT re-reading feat: row[k] broadcast via __shfl_sync.
// 256 threads = 8 warps; warp handles 4 nodes (32 nodes/block, 3125 blocks).
// Block 0 zeroes g_lnacc[par^1] for the NEXT iteration's stats.
#define WTP 130
__global__ void __launch_bounds__(256, 4) k_spmm_gemm(
        int sbuf, float* __restrict__ dout, int last, int par,
        const float* __restrict__ tau1, const float* __restrict__ tau2,
        const float* __restrict__ w, const float* __restrict__ b) {
    __shared__ __align__(8) float ws_t[CC][WTP];   // ~33 KB transposed [c][k]
    int tid = threadIdx.x;
    if (blockIdx.x == 0 && tid < 4) g_lnacc[par ^ 1][tid] = 0ll;

    if (!last) {
        for (int i = tid; i < HH * CC / 4; i += 256) {
            float4 v = ((const float4*)w)[i];
            int k = i >> 4;
            int c = (i & 15) * 4;
            ws_t[c + 0][k] = v.x; ws_t[c + 1][k] = v.y;
            ws_t[c + 2][k] = v.z; ws_t[c + 3][k] = v.w;
        }
        __syncthreads();
    }

    // LN finalize from exact int64 sums (deterministic)
    const float invN = 1.0f / (float)NN;
    float S0 = (float)g_lnacc[par][0] * LN_INVSCALE;
    float S1 = (float)g_lnacc[par][1] * LN_INVSCALE;
    float S2 = (float)g_lnacc[par][2] * LN_INVSCALE;
    float S3 = (float)g_lnacc[par][3] * LN_INVSCALE;
    float m1 = S0 * invN;
    float vv1 = S1 * invN - m1 * m1;
    float m2 = S2 * invN;
    float vv2 = S3 * invN - m2 * m2;
    float r1 = rsqrtf(vv1 + 1e-5f);
    float r2 = rsqrtf(vv2 + 1e-5f);
    float t1 = tau1[0], t2 = tau2[0];

    int wp = tid >> 5, lane = tid & 31;
    int nbase = blockIdx.x * 32 + wp * 4;
    const float* __restrict__ Fs = sbuf ? g_featB : g_featA;
    float* __restrict__ Fd = last ? dout : (sbuf ? g_featA : g_featB);

    float4 rows[4];
    #pragma unroll
    for (int j = 0; j < 4; j++) {
        int n = nbase + j;
        int rs = g_rowstart[n], re = g_rowstart[n + 1];
        float4 own = ((const float4*)(Fs + (size_t)n * HH))[lane];
        float4 acc = make_float4(0.f, 0.f, 0.f, 0.f);
        int idx = rs;
        for (; idx + 4 <= re; idx += 4) {
            int s0 = g_csr[idx], s1 = g_csr[idx + 1], s2 = g_csr[idx + 2], s3 = g_csr[idx + 3];
            float4 v0 = __ldg((const float4*)(Fs + (size_t)s0 * HH) + lane);
            float4 v1 = __ldg((const float4*)(Fs + (size_t)s1 * HH) + lane);
            float4 v2 = __ldg((const float4*)(Fs + (size_t)s2 * HH) + lane);
            float4 v3 = __ldg((const float4*)(Fs + (size_t)s3 * HH) + lane);
            acc.x += (v0.x + v1.x) + (v2.x + v3.x);
            acc.y += (v0.y + v1.y) + (v2.y + v3.y);
            acc.z += (v0.z + v1.z) + (v2.z + v3.z);
            acc.w += (v0.w + v1.w) + (v2.w + v3.w);
        }
        for (; idx < re; idx++) {
            int s = g_csr[idx];
            float4 v = __ldg((const float4*)(Fs + (size_t)s * HH) + lane);
            acc.x += v.x; acc.y += v.y; acc.z += v.z; acc.w += v.w;
        }

        float z1 = 1.0f / (1.0f + expf((g_f1[n] - m1) * r1 - t1));
        float z2 = 1.0f / (1.0f + expf((g_f2[n] - m2) * r2 - t2));
        float z = z1 * z2;
        float nm = g_norm[n];
        float s_agg = last ? (z * nm) : (z * nm * nm);
        float s_own = last ? 1.0f : nm;

        float4 o;
        o.x = s_agg * acc.x + s_own * own.x;
        o.y = s_agg * acc.y + s_own * own.y;
        o.z = s_agg * acc.z + s_own * own.z;
        o.w = s_agg * acc.w + s_own * own.w;
        __stcs((float4*)(Fd + (size_t)n * HH) + lane, o);
        rows[j] = o;
    }

    if (last) return;

    // --- GEMM + argmax on the fresh rows (no global feat re-read) ---
    u64 acc0[4], acc1[4];
    #pragma unroll
    for (int j = 0; j < 4; j++) { acc0[j] = 0ull; acc1[j] = 0ull; }

    const u64* w0p = (const u64*)&ws_t[lane][0];
    const u64* w1p = (const u64*)&ws_t[lane + 32][0];

    #pragma unroll 4
    for (int k4 = 0; k4 < HH / 4; k4++) {
        u64 wa0 = w0p[2 * k4], wa1 = w0p[2 * k4 + 1];
        u64 wb0 = w1p[2 * k4], wb1 = w1p[2 * k4 + 1];
        #pragma unroll
        for (int j = 0; j < 4; j++) {
            float4 f;
            f.x = __shfl_sync(0xffffffffu, rows[j].x, k4);
            f.y = __shfl_sync(0xffffffffu, rows[j].y, k4);
            f.z = __shfl_sync(0xffffffffu, rows[j].z, k4);
            f.w = __shfl_sync(0xffffffffu, rows[j].w, k4);
            u64 fp0 = pk(f.x, f.y);
            u64 fp1 = pk(f.z, f.w);
            acc0[j] = ffma2(fp0, wa0, acc0[j]);
            acc0[j] = ffma2(fp1, wa1, acc0[j]);
            acc1[j] = ffma2(fp0, wb0, acc1[j]);
            acc1[j] = ffma2(fp1, wb1, acc1[j]);
        }
    }

    float bias0 = b[lane], bias1 = b[lane + 32];
    #pragma unroll
    for (int j = 0; j < 4; j++) {
        float2 a0 = upk(acc0[j]);
        float2 a1 = upk(acc1[j]);
        float l0 = (a0.x + a0.y) + bias0;
        float l1 = (a1.x + a1.y) + bias1;
        float bv; int bc;
        if (l1 > l0) { bv = l1; bc = lane + 32; } else { bv = l0; bc = lane; }
        #pragma unroll
        for (int off = 16; off; off >>= 1) {
            float ov = __shfl_down_sync(0xffffffffu, bv, off);
            int   oc = __shfl_down_sync(0xffffffffu, bc, off);
            if (ov > bv || (ov == bv && oc < bc)) { bv = ov; bc = oc; }
        }
        if (lane == 0) g_pred[nbase + j] = bc;
    }
}

// ---------------- host launcher ----------------
extern "C" void kernel_launch(void* const* d_in, const int* in_sizes, int n_in,
                              void* d_out, int out_size) {
    const float* feat   = (const float*)d_in[0];
    const float* logits = (const float*)d_in[1];
    const float* w_y    = (const float*)d_in[2];
    const float* b_y    = (const float*)d_in[3];
    const float* tau1   = (const float*)d_in[4];
    const float* tau2   = (const float*)d_in[5];
    const int*   src    = (const int*)d_in[6];
    const int*   dst    = (const int*)d_in[7];
    float* out = (float*)d_out;
    (void)in_sizes; (void)n_in; (void)out_size;

    const int NB1 = (NN + 1023) / 1024;

    k_zero<<<(NN + 255) / 256, 256>>>();
    k_deg<<<(EE + 255) / 256, 256>>>(dst);
    k_norm<<<(NN + 255) / 256, 256>>>();
    k_scan1<<<NB1, 1024>>>();
    k_scan2<<<1, 1>>>(NB1);
    k_scan3<<<(NN + 255) / 256, 256>>>();
    k_csrfill<<<(EE + 255) / 256, 256>>>(src, dst);
    k_init<<<(NN * (HH / 4) + 255) / 256, 256>>>(feat);

    const int warp_blocks = (NN * 32 + 255) / 256;
    k_argmax0<<<warp_blocks, 256>>>(logits);   // pred(0)

    for (int i = 0; i < KK; i++) {
        int par = i & 1;
        k_stats<<<NN / 32, 1024>>>(par);                 // f1/f2(i) from pred(i)
        k_spmm_gemm<<<NN / 32, 256>>>(par, out, (i == KK - 1) ? 1 : 0, par,
                                      tau1, tau2, w_y, b_y);  // feat(i+1) + pred(i+1)
    }
}

// round 15
// speedup vs baseline: 1.1262x; 1.1262x over previous
#include <cuda_runtime.h>
#include <math.h>

#define NN 100000
#define EE 1600000
#define HH 128
#define CC 64
#define KK 10

typedef unsigned long long u64;
typedef long long s64;

#define LN_SCALE   16777216.0        /* 2^24 */
#define LN_INVSCALE 5.9604644775390625e-8f

// ---------------- device scratch (allocation-free workaround) ----------------
__device__ __align__(16) float g_featA[NN * HH];
__device__ __align__(16) float g_featB[NN * HH];
__device__ int   g_deg[NN];
__device__ float g_norm[NN];
__device__ float g_invdeg[NN];
__device__ int   g_scan[NN];
__device__ int   g_bsum[128];
__device__ int   g_rowstart[NN + 1];
__device__ int   g_rowcur[NN];
__device__ int   g_csr[EE];
__device__ int   g_pred[NN];
__device__ float g_f1[NN];
__device__ float g_f2[NN];
__device__ s64   g_lnacc[4];   // scaled-int accumulators: S(f1), S(f1^2), S(f2), S(f2^2) * 2^24

// ---------------- packed fp32x2 helpers ----------------
__device__ __forceinline__ u64 ffma2(u64 a, u64 b, u64 c) {
    u64 d;
    asm("fma.rn.f32x2 %0, %1, %2, %3;" : "=l"(d) : "l"(a), "l"(b), "l"(c));
    return d;
}
__device__ __forceinline__ u64 pk(float x, float y) {
    u64 d;
    asm("mov.b64 %0, {%1, %2};" : "=l"(d) : "f"(x), "f"(y));
    return d;
}
__device__ __forceinline__ float2 upk(u64 v) {
    float2 r;
    asm("mov.b64 {%0, %1}, %2;" : "=f"(r.x), "=f"(r.y) : "l"(v));
    return r;
}

// ---------------- setup kernels ----------------
__global__ void k_zero() {
    int i = blockIdx.x * blockDim.x + threadIdx.x;
    if (i < NN) { g_deg[i] = 0; g_rowcur[i] = 0; }
}

__global__ void k_deg(const int* __restrict__ dst) {
    int e = blockIdx.x * blockDim.x + threadIdx.x;
    if (e < EE) atomicAdd(&g_deg[dst[e]], 1);
}

__global__ void k_norm() {
    int i = blockIdx.x * blockDim.x + threadIdx.x;
    if (i < NN) {
        int d = g_deg[i];
        float dc = (d > 0) ? (float)d : 1.0f;
        g_norm[i] = rsqrtf(dc);
        g_invdeg[i] = 1.0f / dc;
    }
}

// inclusive scan within 1024-element blocks
__global__ void k_scan1() {
    __shared__ int sh[1024];
    int tid = threadIdx.x;
    int i = blockIdx.x * 1024 + tid;
    int v = (i < NN) ? g_deg[i] : 0;
    sh[tid] = v;
    __syncthreads();
    for (int off = 1; off < 1024; off <<= 1) {
        int t = (tid >= off) ? sh[tid - off] : 0;
        __syncthreads();
        sh[tid] += t;
        __syncthreads();
    }
    if (i < NN) g_scan[i] = sh[tid];
    if (tid == 1023) g_bsum[blockIdx.x] = sh[1023];
}

__global__ void k_scan2(int nb) {
    int run = 0;
    for (int b = 0; b < nb; b++) { int t = g_bsum[b]; g_bsum[b] = run; run += t; }
}

__global__ void k_scan3() {
    int i = blockIdx.x * blockDim.x + threadIdx.x;
    if (i < NN) g_rowstart[i] = g_scan[i] - g_deg[i] + g_bsum[i >> 10];
    if (i == 0) g_rowstart[NN] = EE;
}

__global__ void k_csrfill(const int* __restrict__ src, const int* __restrict__ dst) {
    int e = blockIdx.x * blockDim.x + threadIdx.x;
    if (e < EE) {
        int d = dst[e];
        int pos = g_rowstart[d] + atomicAdd(&g_rowcur[d], 1);
        g_csr[pos] = src[e];
    }
}

// feat buffer initialized to pre-scaled feat: Fs(0) = feat_in * norm
__global__ void k_init(const float* __restrict__ fin) {
    int i = blockIdx.x * blockDim.x + threadIdx.x;
    if (i < NN * (HH / 4)) {
        int n = i >> 5;
        float nm = g_norm[n];
        float4 v = ((const float4*)fin)[i];
        v.x *= nm; v.y *= nm; v.z *= nm; v.w *= nm;
        ((float4*)g_featA)[i] = v;
    }
}

// ---------------- per-iteration kernels ----------------

// iteration 0: argmax over the input logits (block 0 zeroes LN accumulators)
__global__ void k_argmax0(const float* __restrict__ logits) {
    if (blockIdx.x == 0 && threadIdx.x < 4) g_lnacc[threadIdx.x] = 0ll;
    int n = (blockIdx.x * blockDim.x + threadIdx.x) >> 5;
    int lane = threadIdx.x & 31;
    if (n >= NN) return;
    const float* row = logits + (size_t)n * CC;
    float v0 = row[lane], v1 = row[lane + 32];
    float bv; int bc;
    if (v1 > v0) { bv = v1; bc = lane + 32; } else { bv = v0; bc = lane; }
    #pragma unroll
    for (int off = 16; off; off >>= 1) {
        float ov = __shfl_down_sync(0xffffffffu, bv, off);
        int   oc = __shfl_down_sync(0xffffffffu, bc, off);
        if (ov > bv || (ov == bv && oc < bc)) { bv = ov; bc = oc; }
    }
    if (lane == 0) g_pred[n] = bc;
}

// iterations 1..: fused GEMM (scaled feat @ w_y + b_y) + row argmax.
// K-packed FFMA2, 320 threads = 10 warps x 8 nodes = 80 nodes/block,
// exactly 1250 blocks: w-traffic 40MB/iter (was 100MB), 30 warps/SM resident.
// Block 0 zeroes LN accumulators for the k_stats that follows.
#define WTP 130
#define GW  10   /* warps per gemm block */
__global__ void __launch_bounds__(32 * GW) k_gemm_argmax(int sbuf, const float* __restrict__ w,
                                                         const float* __restrict__ b) {
    __shared__ __align__(8) float ws_t[CC][WTP];           // ~32.5 KB transposed [c][k]
    __shared__ __align__(16) float4 srow[GW][8][HH / 4];   // 40 KB
    const float* __restrict__ F = sbuf ? g_featB : g_featA;
    int tid = threadIdx.x;
    if (blockIdx.x == 0 && tid < 4) g_lnacc[tid] = 0ll;

    for (int i = tid; i < HH * CC / 4; i += 32 * GW) {
        float4 v = ((const float4*)w)[i];
        int k = i >> 4;
        int c = (i & 15) * 4;
        ws_t[c + 0][k] = v.x; ws_t[c + 1][k] = v.y;
        ws_t[c + 2][k] = v.z; ws_t[c + 3][k] = v.w;
    }
    __syncthreads();

    int wp = tid >> 5, lane = tid & 31;
    int base = blockIdx.x * (8 * GW) + wp * 8;

    float4 tmp[8];
    #pragma unroll
    for (int r = 0; r < 8; r++)
        tmp[r] = __ldg((const float4*)(F + (size_t)(base + r) * HH) + lane);
    #pragma unroll
    for (int r = 0; r < 8; r++)
        srow[wp][r][lane] = tmp[r];
    __syncwarp();

    u64 acc0[8], acc1[8];
    #pragma unroll
    for (int r = 0; r < 8; r++) { acc0[r] = 0ull; acc1[r] = 0ull; }

    const u64* w0p = (const u64*)&ws_t[lane][0];
    const u64* w1p = (const u64*)&ws_t[lane + 32][0];
    const float4* fr = &srow[wp][0][0];

    #pragma unroll 4
    for (int k4 = 0; k4 < HH / 4; k4++) {
        u64 wa0 = w0p[2 * k4], wa1 = w0p[2 * k4 + 1];
        u64 wb0 = w1p[2 * k4], wb1 = w1p[2 * k4 + 1];
        #pragma unroll
        for (int r = 0; r < 8; r++) {
            float4 f = fr[r * (HH / 4) + k4];
            u64 fp0 = pk(f.x, f.y);
            u64 fp1 = pk(f.z, f.w);
            acc0[r] = ffma2(fp0, wa0, acc0[r]);
            acc0[r] = ffma2(fp1, wa1, acc0[r]);
            acc1[r] = ffma2(fp0, wb0, acc1[r]);
            acc1[r] = ffma2(fp1, wb1, acc1[r]);
        }
    }

    float bias0 = b[lane], bias1 = b[lane + 32];
    #pragma unroll
    for (int r = 0; r < 8; r++) {
        float2 a0 = upk(acc0[r]);
        float2 a1 = upk(acc1[r]);
        float l0 = (a0.x + a0.y) + bias0;
        float l1 = (a1.x + a1.y) + bias1;
        float bv; int bc;
        if (l1 > l0) { bv = l1; bc = lane + 32; } else { bv = l0; bc = lane; }
        #pragma unroll
        for (int off = 16; off; off >>= 1) {
            float ov = __shfl_down_sync(0xffffffffu, bv, off);
            int   oc = __shfl_down_sync(0xffffffffu, bc, off);
            if (ov > bv || (ov == bv && oc < bc)) { bv = ov; bc = oc; }
        }
        if (lane == 0) g_pred[base + r] = bc;
    }
}

// fused neighborhood stats: f1 (agreement) + f2 (entropy of class histogram).
// Per-block LN partials quantized to 2^-24 and accumulated with INT64 atomics:
// bit-exact, order-independent, native RED.64. No fence, no tail block.
__global__ void k_stats() {
    __shared__ int hist[32][CC];
    __shared__ float4 red[32];
    int tid = threadIdx.x, w = tid >> 5, lane = tid & 31;
    int n = blockIdx.x * 32 + w;
    hist[w][lane] = 0; hist[w][lane + 32] = 0;
    __syncwarp();
    int pd = g_pred[n];
    int rs = g_rowstart[n], re = g_rowstart[n + 1];
    int eq = 0;
    for (int idx = rs + lane; idx < re; idx += 32) {
        int ps = g_pred[g_csr[idx]];
        eq += (ps == pd);
        atomicAdd(&hist[w][ps], 1);
    }
    __syncwarp();
    #pragma unroll
    for (int off = 16; off; off >>= 1) eq += __shfl_down_sync(0xffffffffu, eq, off);
    float inv = g_invdeg[n];
    float p0 = fmaxf((float)hist[w][lane] * inv, 1e-5f);
    float p1 = fmaxf((float)hist[w][lane + 32] * inv, 1e-5f);
    float ent = -(p0 * logf(p0) + p1 * logf(p1));
    #pragma unroll
    for (int off = 16; off; off >>= 1) ent += __shfl_down_sync(0xffffffffu, ent, off);
    if (lane == 0) {
        float f1 = (float)eq * inv;
        g_f1[n] = f1; g_f2[n] = ent;
        red[w] = make_float4(f1, f1 * f1, ent, ent * ent);
    }
    __syncthreads();
    if (tid < 4) {
        float s = 0.0f;
        #pragma unroll
        for (int ww = 0; ww < 32; ww++) s += ((const float*)&red[ww])[tid];
        s64 q = __double2ll_rn((double)s * LN_SCALE);
        atomicAdd((u64*)&g_lnacc[tid], (u64)q);
    }
}

// fused SpMM gather + gate + combine + (folded) next-iteration scale (fp32).
// LN finalize per thread from the exact int64 sums: deterministic, cheap.
// 4-deep gather batches (proven best depth).
__global__ void k_spmm(int sbuf, float* __restrict__ dout, int last,
                       const float* __restrict__ tau1, const float* __restrict__ tau2) {
    const float invN = 1.0f / (float)NN;
    float S0 = (float)g_lnacc[0] * LN_INVSCALE;
    float S1 = (float)g_lnacc[1] * LN_INVSCALE;
    float S2 = (float)g_lnacc[2] * LN_INVSCALE;
    float S3 = (float)g_lnacc[3] * LN_INVSCALE;
    float m1 = S0 * invN;
    float v1 = S1 * invN - m1 * m1;
    float m2 = S2 * invN;
    float v2 = S3 * invN - m2 * m2;
    float r1 = rsqrtf(v1 + 1e-5f);
    float r2 = rsqrtf(v2 + 1e-5f);

    int n = (blockIdx.x * blockDim.x + threadIdx.x) >> 5;
    int lane = threadIdx.x & 31;
    if (n >= NN) return;
    const float* __restrict__ Fs = sbuf ? g_featB : g_featA;
    float* __restrict__ Fd = last ? dout : (sbuf ? g_featA : g_featB);

    int rs = g_rowstart[n], re = g_rowstart[n + 1];
    float4 own = ((const float4*)(Fs + (size_t)n * HH))[lane];
    float4 acc = make_float4(0.f, 0.f, 0.f, 0.f);
    int idx = rs;
    for (; idx + 4 <= re; idx += 4) {
        int s0 = g_csr[idx], s1 = g_csr[idx + 1], s2 = g_csr[idx + 2], s3 = g_csr[idx + 3];
        float4 v0 = __ldg((const float4*)(Fs + (size_t)s0 * HH) + lane);
        float4 v1v = __ldg((const float4*)(Fs + (size_t)s1 * HH) + lane);
        float4 v2v = __ldg((const float4*)(Fs + (size_t)s2 * HH) + lane);
        float4 v3v = __ldg((const float4*)(Fs + (size_t)s3 * HH) + lane);
        acc.x += (v0.x + v1v.x) + (v2v.x + v3v.x);
        acc.y += (v0.y + v1v.y) + (v2v.y + v3v.y);
        acc.z += (v0.z + v1v.z) + (v2v.z + v3v.z);
        acc.w += (v0.w + v1v.w) + (v2v.w + v3v.w);
    }
    for (; idx < re; idx++) {
        int s = g_csr[idx];
        float4 v = __ldg((const float4*)(Fs + (size_t)s * HH) + lane);
        acc.x += v.x; acc.y += v.y; acc.z += v.z; acc.w += v.w;
    }

    float z1 = 1.0f / (1.0f + expf((g_f1[n] - m1) * r1 - tau1[0]));
    float z2 = 1.0f / (1.0f + expf((g_f2[n] - m2) * r2 - tau2[0]));
    float z = z1 * z2;
    float nm = g_norm[n];
    float s_agg = last ? (z * nm) : (z * nm * nm);
    float s_own = last ? 1.0f : nm;

    float4 o;
    o.x = s_agg * acc.x + s_own * own.x;
    o.y = s_agg * acc.y + s_own * own.y;
    o.z = s_agg * acc.z + s_own * own.z;
    o.w = s_agg * acc.w + s_own * own.w;
    __stcs((float4*)(Fd + (size_t)n * HH) + lane, o);
}

// ---------------- host launcher ----------------
extern "C" void kernel_launch(void* const* d_in, const int* in_sizes, int n_in,
                              void* d_out, int out_size) {
    const float* feat   = (const float*)d_in[0];
    const float* logits = (const float*)d_in[1];
    const float* w_y    = (const float*)d_in[2];
    const float* b_y    = (const float*)d_in[3];
    const float* tau1   = (const float*)d_in[4];
    const float* tau2   = (const float*)d_in[5];
    const int*   src    = (const int*)d_in[6];
    const int*   dst    = (const int*)d_in[7];
    float* out = (float*)d_out;
    (void)in_sizes; (void)n_in; (void)out_size;

    const int NB1 = (NN + 1023) / 1024;

    k_zero<<<(NN + 255) / 256, 256>>>();
    k_deg<<<(EE + 255) / 256, 256>>>(dst);
    k_norm<<<(NN + 255) / 256, 256>>>();
    k_scan1<<<NB1, 1024>>>();
    k_scan2<<<1, 1>>>(NB1);
    k_scan3<<<(NN + 255) / 256, 256>>>();
    k_csrfill<<<(EE + 255) / 256, 256>>>(src, dst);
    k_init<<<(NN * (HH / 4) + 255) / 256, 256>>>(feat);

    const int warp_blocks = (NN * 32 + 255) / 256;
    for (int i = 0; i < KK; i++) {
        int sbuf = i & 1;
        if (i == 0) {
            k_argmax0<<<warp_blocks, 256>>>(logits);
        } else {
            k_gemm_argmax<<<NN / 80, 32 * GW>>>(sbuf, w_y, b_y);  // 1250 blocks
        }
        k_stats<<<NN / 32, 1024>>>();
        k_spmm<<<warp_blocks, 256>>>(sbuf, out, (i == KK - 1) ? 1 : 0, tau1, tau2);
    }
}

// round 16
// speedup vs baseline: 1.1425x; 1.0144x over previous
#include <cuda_runtime.h>
#include <math.h>

#define NN 100000
#define EE 1600000
#define HH 128
#define CC 64
#define KK 10

typedef unsigned long long u64;
typedef long long s64;

#define LN_SCALE   16777216.0        /* 2^24 */
#define LN_INVSCALE 5.9604644775390625e-8f

// ---------------- device scratch (allocation-free workaround) ----------------
__device__ __align__(16) float g_featA[NN * HH];
__device__ __align__(16) float g_featB[NN * HH];
__device__ int   g_deg[NN];
__device__ float g_norm[NN];
__device__ float g_invdeg[NN];
__device__ int   g_scan[NN];
__device__ int   g_bsum[128];
__device__ int   g_rowstart[NN + 1];
__device__ int   g_rowcur[NN];
__device__ int   g_csr[EE];
__device__ int   g_pred[NN];
__device__ float g_f1[NN];
__device__ float g_f2[NN];
__device__ s64   g_lnacc[4];   // scaled-int LN sums: S(f1), S(f1^2), S(f2), S(f2^2) * 2^24

// ---------------- packed fp32x2 helpers ----------------
__device__ __forceinline__ u64 ffma2(u64 a, u64 b, u64 c) {
    u64 d;
    asm("fma.rn.f32x2 %0, %1, %2, %3;" : "=l"(d) : "l"(a), "l"(b), "l"(c));
    return d;
}
__device__ __forceinline__ u64 pk(float x, float y) {
    u64 d;
    asm("mov.b64 %0, {%1, %2};" : "=l"(d) : "f"(x), "f"(y));
    return d;
}
__device__ __forceinline__ float2 upk(u64 v) {
    float2 r;
    asm("mov.b64 {%0, %1}, %2;" : "=f"(r.x), "=f"(r.y) : "l"(v));
    return r;
}

// ---------------- setup kernels ----------------
__global__ void k_zero() {
    int i = blockIdx.x * blockDim.x + threadIdx.x;
    if (i < NN) { g_deg[i] = 0; g_rowcur[i] = 0; }
}

__global__ void k_deg(const int* __restrict__ dst) {
    int e = blockIdx.x * blockDim.x + threadIdx.x;
    if (e < EE) atomicAdd(&g_deg[dst[e]], 1);
}

__global__ void k_norm() {
    int i = blockIdx.x * blockDim.x + threadIdx.x;
    if (i < NN) {
        int d = g_deg[i];
        float dc = (d > 0) ? (float)d : 1.0f;
        g_norm[i] = rsqrtf(dc);
        g_invdeg[i] = 1.0f / dc;
    }
}

// inclusive scan within 1024-element blocks
__global__ void k_scan1() {
    __shared__ int sh[1024];
    int tid = threadIdx.x;
    int i = blockIdx.x * 1024 + tid;
    int v = (i < NN) ? g_deg[i] : 0;
    sh[tid] = v;
    __syncthreads();
    for (int off = 1; off < 1024; off <<= 1) {
        int t = (tid >= off) ? sh[tid - off] : 0;
        __syncthreads();
        sh[tid] += t;
        __syncthreads();
    }
    if (i < NN) g_scan[i] = sh[tid];
    if (tid == 1023) g_bsum[blockIdx.x] = sh[1023];
}

__global__ void k_scan2(int nb) {
    int run = 0;
    for (int b = 0; b < nb; b++) { int t = g_bsum[b]; g_bsum[b] = run; run += t; }
}

__global__ void k_scan3() {
    int i = blockIdx.x * blockDim.x + threadIdx.x;
    if (i < NN) g_rowstart[i] = g_scan[i] - g_deg[i] + g_bsum[i >> 10];
    if (i == 0) g_rowstart[NN] = EE;
}

__global__ void k_csrfill(const int* __restrict__ src, const int* __restrict__ dst) {
    int e = blockIdx.x * blockDim.x + threadIdx.x;
    if (e < EE) {
        int d = dst[e];
        int pos = g_rowstart[d] + atomicAdd(&g_rowcur[d], 1);
        g_csr[pos] = src[e];
    }
}

// feat buffer initialized to pre-scaled feat: Fs(0) = feat_in * norm
__global__ void k_init(const float* __restrict__ fin) {
    int i = blockIdx.x * blockDim.x + threadIdx.x;
    if (i < NN * (HH / 4)) {
        int n = i >> 5;
        float nm = g_norm[n];
        float4 v = ((const float4*)fin)[i];
        v.x *= nm; v.y *= nm; v.z *= nm; v.w *= nm;
        ((float4*)g_featA)[i] = v;
    }
}

// ---------------- per-iteration kernels ----------------

// iteration 0: argmax over the input logits (block 0 zeroes LN accumulators)
__global__ void k_argmax0(const float* __restrict__ logits) {
    if (blockIdx.x == 0 && threadIdx.x < 4) g_lnacc[threadIdx.x] = 0ll;
    int n = (blockIdx.x * blockDim.x + threadIdx.x) >> 5;
    int lane = threadIdx.x & 31;
    if (n >= NN) return;
    const float* row = logits + (size_t)n * CC;
    float v0 = row[lane], v1 = row[lane + 32];
    float bv; int bc;
    if (v1 > v0) { bv = v1; bc = lane + 32; } else { bv = v0; bc = lane; }
    #pragma unroll
    for (int off = 16; off; off >>= 1) {
        float ov = __shfl_down_sync(0xffffffffu, bv, off);
        int   oc = __shfl_down_sync(0xffffffffu, bc, off);
        if (ov > bv || (ov == bv && oc < bc)) { bv = ov; bc = oc; }
    }
    if (lane == 0) g_pred[n] = bc;
}

// iterations 1..: fused GEMM (scaled feat @ w_y + b_y) + row argmax.
// K-packed FFMA2, 10 warps x 8 nodes = 80 nodes/block, 1250 blocks (R15 proven).
// Block 0 zeroes LN accumulators for the mega kernel that follows.
#define WTP 130
#define GW  10
__global__ void __launch_bounds__(32 * GW) k_gemm_argmax(int sbuf, const float* __restrict__ w,
                                                         const float* __restrict__ b) {
    __shared__ __align__(8) float ws_t[CC][WTP];
    __shared__ __align__(16) float4 srow[GW][8][HH / 4];
    const float* __restrict__ F = sbuf ? g_featB : g_featA;
    int tid = threadIdx.x;
    if (blockIdx.x == 0 && tid < 4) g_lnacc[tid] = 0ll;

    for (int i = tid; i < HH * CC / 4; i += 32 * GW) {
        float4 v = ((const float4*)w)[i];
        int k = i >> 4;
        int c = (i & 15) * 4;
        ws_t[c + 0][k] = v.x; ws_t[c + 1][k] = v.y;
        ws_t[c + 2][k] = v.z; ws_t[c + 3][k] = v.w;
    }
    __syncthreads();

    int wp = tid >> 5, lane = tid & 31;
    int base = blockIdx.x * (8 * GW) + wp * 8;

    float4 tmp[8];
    #pragma unroll
    for (int r = 0; r < 8; r++)
        tmp[r] = __ldg((const float4*)(F + (size_t)(base + r) * HH) + lane);
    #pragma unroll
    for (int r = 0; r < 8; r++)
        srow[wp][r][lane] = tmp[r];
    __syncwarp();

    u64 acc0[8], acc1[8];
    #pragma unroll
    for (int r = 0; r < 8; r++) { acc0[r] = 0ull; acc1[r] = 0ull; }

    const u64* w0p = (const u64*)&ws_t[lane][0];
    const u64* w1p = (const u64*)&ws_t[lane + 32][0];
    const float4* fr = &srow[wp][0][0];

    #pragma unroll 4
    for (int k4 = 0; k4 < HH / 4; k4++) {
        u64 wa0 = w0p[2 * k4], wa1 = w0p[2 * k4 + 1];
        u64 wb0 = w1p[2 * k4], wb1 = w1p[2 * k4 + 1];
        #pragma unroll
        for (int r = 0; r < 8; r++) {
            float4 f = fr[r * (HH / 4) + k4];
            u64 fp0 = pk(f.x, f.y);
            u64 fp1 = pk(f.z, f.w);
            acc0[r] = ffma2(fp0, wa0, acc0[r]);
            acc0[r] = ffma2(fp1, wa1, acc0[r]);
            acc1[r] = ffma2(fp0, wb0, acc1[r]);
            acc1[r] = ffma2(fp1, wb1, acc1[r]);
        }
    }

    float bias0 = b[lane], bias1 = b[lane + 32];
    #pragma unroll
    for (int r = 0; r < 8; r++) {
        float2 a0 = upk(acc0[r]);
        float2 a1 = upk(acc1[r]);
        float l0 = (a0.x + a0.y) + bias0;
        float l1 = (a1.x + a1.y) + bias1;
        float bv; int bc;
        if (l1 > l0) { bv = l1; bc = lane + 32; } else { bv = l0; bc = lane; }
        #pragma unroll
        for (int off = 16; off; off >>= 1) {
            float ov = __shfl_down_sync(0xffffffffu, bv, off);
            int   oc = __shfl_down_sync(0xffffffffu, bc, off);
            if (ov > bv || (ov == bv && oc < bc)) { bv = ov; bc = oc; }
        }
        if (lane == 0) g_pred[base + r] = bc;
    }
}

// INTERLEAVED mega-kernel: odd blocks = neighborhood stats (f1/f2 + int64 LN
// partials), even blocks = raw SpMM gather (agg[n] = sum feat[src]) into the
// opposite buffer. Parity interleave -> both kinds co-resident, stats latency
// hides under the gather's memory-bound issue slack. 256 thr, warp-per-node.
__global__ void k_mega(int sbuf) {
    __shared__ int hist[8][CC];
    __shared__ float4 red[8];
    int tid = threadIdx.x, wp = tid >> 5, lane = tid & 31;
    int grp = blockIdx.x >> 1;
    int n = grp * 8 + wp;

    if (blockIdx.x & 1) {
        // ---- stats ----
        hist[wp][lane] = 0; hist[wp][lane + 32] = 0;
        __syncwarp();
        int pd = g_pred[n];
        int rs = g_rowstart[n], re = g_rowstart[n + 1];
        int eq = 0;
        for (int idx = rs + lane; idx < re; idx += 32) {
            int ps = g_pred[g_csr[idx]];
            eq += (ps == pd);
            atomicAdd(&hist[wp][ps], 1);
        }
        __syncwarp();
        #pragma unroll
        for (int off = 16; off; off >>= 1) eq += __shfl_down_sync(0xffffffffu, eq, off);
        float inv = g_invdeg[n];
        float p0 = fmaxf((float)hist[wp][lane] * inv, 1e-5f);
        float p1 = fmaxf((float)hist[wp][lane + 32] * inv, 1e-5f);
        float ent = -(p0 * logf(p0) + p1 * logf(p1));
        #pragma unroll
        for (int off = 16; off; off >>= 1) ent += __shfl_down_sync(0xffffffffu, ent, off);
        if (lane == 0) {
            float f1 = (float)eq * inv;
            g_f1[n] = f1; g_f2[n] = ent;
            red[wp] = make_float4(f1, f1 * f1, ent, ent * ent);
        }
        __syncthreads();
        if (tid < 4) {
            float s = 0.0f;
            #pragma unroll
            for (int ww = 0; ww < 8; ww++) s += ((const float*)&red[ww])[tid];
            s64 q = __double2ll_rn((double)s * LN_SCALE);
            atomicAdd((u64*)&g_lnacc[tid], (u64)q);
        }
    } else {
        // ---- raw gather ----
        const float* __restrict__ Fs = sbuf ? g_featB : g_featA;
        float* __restrict__ Fa = sbuf ? g_featA : g_featB;
        int rs = g_rowstart[n], re = g_rowstart[n + 1];
        float4 acc = make_float4(0.f, 0.f, 0.f, 0.f);
        int idx = rs;
        for (; idx + 4 <= re; idx += 4) {
            int s0 = g_csr[idx], s1 = g_csr[idx + 1], s2 = g_csr[idx + 2], s3 = g_csr[idx + 3];
            float4 v0 = __ldg((const float4*)(Fs + (size_t)s0 * HH) + lane);
            float4 v1 = __ldg((const float4*)(Fs + (size_t)s1 * HH) + lane);
            float4 v2 = __ldg((const float4*)(Fs + (size_t)s2 * HH) + lane);
            float4 v3 = __ldg((const float4*)(Fs + (size_t)s3 * HH) + lane);
            acc.x += (v0.x + v1.x) + (v2.x + v3.x);
            acc.y += (v0.y + v1.y) + (v2.y + v3.y);
            acc.z += (v0.z + v1.z) + (v2.z + v3.z);
            acc.w += (v0.w + v1.w) + (v2.w + v3.w);
        }
        for (; idx < re; idx++) {
            int s = g_csr[idx];
            float4 v = __ldg((const float4*)(Fs + (size_t)s * HH) + lane);
            acc.x += v.x; acc.y += v.y; acc.z += v.z; acc.w += v.w;
        }
        ((float4*)(Fa + (size_t)n * HH))[lane] = acc;
    }
}

// combine: feat(i+1) = z*nm^2*agg + nm*own (in place over agg), or the final
// out = z*nm*agg + own -> dout. Gate z computed ONCE PER WARP (lane 0 + shfl):
// 200k expf/iter instead of 6.4M. LN finalized from exact int64 sums.
__global__ void k_combine(int sbuf, float* __restrict__ dout, int last,
                          const float* __restrict__ tau1, const float* __restrict__ tau2) {
    int gi = blockIdx.x * blockDim.x + threadIdx.x;   // float4 index, exact grid
    int lane = threadIdx.x & 31;
    int n = gi >> 5;
    const float* __restrict__ Fs = sbuf ? g_featB : g_featA;   // own = feat(i)
    float* __restrict__ Fa = sbuf ? g_featA : g_featB;         // agg in / feat(i+1) out

    float z = 0.0f;
    if (lane == 0) {
        const float invN = 1.0f / (float)NN;
        float S0 = (float)g_lnacc[0] * LN_INVSCALE;
        float S1 = (float)g_lnacc[1] * LN_INVSCALE;
        float S2 = (float)g_lnacc[2] * LN_INVSCALE;
        float S3 = (float)g_lnacc[3] * LN_INVSCALE;
        float m1 = S0 * invN;
        float v1 = S1 * invN - m1 * m1;
        float m2 = S2 * invN;
        float v2 = S3 * invN - m2 * m2;
        float r1 = rsqrtf(v1 + 1e-5f);
        float r2 = rsqrtf(v2 + 1e-5f);
        float z1 = 1.0f / (1.0f + expf((g_f1[n] - m1) * r1 - tau1[0]));
        float z2 = 1.0f / (1.0f + expf((g_f2[n] - m2) * r2 - tau2[0]));
        z = z1 * z2;
    }
    z = __shfl_sync(0xffffffffu, z, 0);

    float nm = g_norm[n];
    float s_agg = last ? (z * nm) : (z * nm * nm);
    float s_own = last ? 1.0f : nm;

    float4 ag = ((const float4*)Fa)[gi];
    float4 ow = __ldg((const float4*)Fs + gi);
    float4 o;
    o.x = s_agg * ag.x + s_own * ow.x;
    o.y = s_agg * ag.y + s_own * ow.y;
    o.z = s_agg * ag.z + s_own * ow.z;
    o.w = s_agg * ag.w + s_own * ow.w;
    if (last) ((float4*)dout)[gi] = o;
    else      ((float4*)Fa)[gi]   = o;
}

// ---------------- host launcher ----------------
extern "C" void kernel_launch(void* const* d_in, const int* in_sizes, int n_in,
                              void* d_out, int out_size) {
    const float* feat   = (const float*)d_in[0];
    const float* logits = (const float*)d_in[1];
    const float* w_y    = (const float*)d_in[2];
    const float* b_y    = (const float*)d_in[3];
    const float* tau1   = (const float*)d_in[4];
    const float* tau2   = (const float*)d_in[5];
    const int*   src    = (const int*)d_in[6];
    const int*   dst    = (const int*)d_in[7];
    float* out = (float*)d_out;
    (void)in_sizes; (void)n_in; (void)out_size;

    const int NB1 = (NN + 1023) / 1024;

    k_zero<<<(NN + 255) / 256, 256>>>();
    k_deg<<<(EE + 255) / 256, 256>>>(dst);
    k_norm<<<(NN + 255) / 256, 256>>>();
    k_scan1<<<NB1, 1024>>>();
    k_scan2<<<1, 1>>>(NB1);
    k_scan3<<<(NN + 255) / 256, 256>>>();
    k_csrfill<<<(EE + 255) / 256, 256>>>(src, dst);
    k_init<<<(NN * (HH / 4) + 255) / 256, 256>>>(feat);

    const int warp_blocks = (NN * 32 + 255) / 256;
    for (int i = 0; i < KK; i++) {
        int sbuf = i & 1;
        if (i == 0) {
            k_argmax0<<<warp_blocks, 256>>>(logits);
        } else {
            k_gemm_argmax<<<NN / 80, 32 * GW>>>(sbuf, w_y, b_y);
        }
        k_mega<<<2 * (NN / 8), 256>>>(sbuf);                         // 25000 blocks
        k_combine<<<NN * (HH / 4) / 256, 256>>>(sbuf, out, (i == KK - 1) ? 1 : 0,
                                                tau1, tau2);
    }
}

// round 17
// speedup vs baseline: 1.2580x; 1.1012x over previous
#include <cuda_runtime.h>
#include <math.h>

#define NN 100000
#define EE 1600000
#define HH 128
#define CC 64
#define KK 10

typedef unsigned long long u64;
typedef long long s64;

#define LN_SCALE   16777216.0        /* 2^24 */
#define LN_INVSCALE 5.9604644775390625e-8f

// ---------------- device scratch (allocation-free workaround) ----------------
__device__ __align__(16) float g_featA[NN * HH];
__device__ __align__(16) float g_featB[NN * HH];
__device__ int   g_deg[NN];
__device__ float g_norm[NN];
__device__ float g_invdeg[NN];
__device__ int   g_scan[NN];
__device__ int   g_bsum[128];
__device__ int   g_rowstart[NN + 1];
__device__ int   g_rowcur[NN];
__device__ int   g_csr[EE];
__device__ int   g_pred[NN];
__device__ float g_f1[NN];
__device__ float g_f2[NN];
__device__ s64   g_lnacc[2][4];   // parity-double-buffered scaled-int LN sums

// ---------------- packed fp32x2 helpers ----------------
__device__ __forceinline__ u64 ffma2(u64 a, u64 b, u64 c) {
    u64 d;
    asm("fma.rn.f32x2 %0, %1, %2, %3;" : "=l"(d) : "l"(a), "l"(b), "l"(c));
    return d;
}
__device__ __forceinline__ u64 pk(float x, float y) {
    u64 d;
    asm("mov.b64 %0, {%1, %2};" : "=l"(d) : "f"(x), "f"(y));
    return d;
}
__device__ __forceinline__ float2 upk(u64 v) {
    float2 r;
    asm("mov.b64 {%0, %1}, %2;" : "=f"(r.x), "=f"(r.y) : "l"(v));
    return r;
}

// ---------------- setup kernels ----------------
__global__ void k_zero() {
    int i = blockIdx.x * blockDim.x + threadIdx.x;
    if (i < NN) { g_deg[i] = 0; g_rowcur[i] = 0; }
    if (i < 8) ((s64*)g_lnacc)[i] = 0ll;
}

__global__ void k_deg(const int* __restrict__ dst) {
    int e = blockIdx.x * blockDim.x + threadIdx.x;
    if (e < EE) atomicAdd(&g_deg[dst[e]], 1);
}

__global__ void k_norm() {
    int i = blockIdx.x * blockDim.x + threadIdx.x;
    if (i < NN) {
        int d = g_deg[i];
        float dc = (d > 0) ? (float)d : 1.0f;
        g_norm[i] = rsqrtf(dc);
        g_invdeg[i] = 1.0f / dc;
    }
}

// inclusive scan within 1024-element blocks
__global__ void k_scan1() {
    __shared__ int sh[1024];
    int tid = threadIdx.x;
    int i = blockIdx.x * 1024 + tid;
    int v = (i < NN) ? g_deg[i] : 0;
    sh[tid] = v;
    __syncthreads();
    for (int off = 1; off < 1024; off <<= 1) {
        int t = (tid >= off) ? sh[tid - off] : 0;
        __syncthreads();
        sh[tid] += t;
        __syncthreads();
    }
    if (i < NN) g_scan[i] = sh[tid];
    if (tid == 1023) g_bsum[blockIdx.x] = sh[1023];
}

__global__ void k_scan2(int nb) {
    int run = 0;
    for (int b = 0; b < nb; b++) { int t = g_bsum[b]; g_bsum[b] = run; run += t; }
}

__global__ void k_scan3() {
    int i = blockIdx.x * blockDim.x + threadIdx.x;
    if (i < NN) g_rowstart[i] = g_scan[i] - g_deg[i] + g_bsum[i >> 10];
    if (i == 0) g_rowstart[NN] = EE;
}

__global__ void k_csrfill(const int* __restrict__ src, const int* __restrict__ dst) {
    int e = blockIdx.x * blockDim.x + threadIdx.x;
    if (e < EE) {
        int d = dst[e];
        int pos = g_rowstart[d] + atomicAdd(&g_rowcur[d], 1);
        g_csr[pos] = src[e];
    }
}

// feat buffer initialized to pre-scaled feat: Fs(0) = feat_in * norm
__global__ void k_init(const float* __restrict__ fin) {
    int i = blockIdx.x * blockDim.x + threadIdx.x;
    if (i < NN * (HH / 4)) {
        int n = i >> 5;
        float nm = g_norm[n];
        float4 v = ((const float4*)fin)[i];
        v.x *= nm; v.y *= nm; v.z *= nm; v.w *= nm;
        ((float4*)g_featA)[i] = v;
    }
}

// ---------------- per-iteration kernels ----------------

// before iteration 0: argmax over the input logits -> pred(0)
__global__ void k_argmax0(const float* __restrict__ logits) {
    int n = (blockIdx.x * blockDim.x + threadIdx.x) >> 5;
    int lane = threadIdx.x & 31;
    if (n >= NN) return;
    const float* row = logits + (size_t)n * CC;
    float v0 = row[lane], v1 = row[lane + 32];
    float bv; int bc;
    if (v1 > v0) { bv = v1; bc = lane + 32; } else { bv = v0; bc = lane; }
    #pragma unroll
    for (int off = 16; off; off >>= 1) {
        float ov = __shfl_down_sync(0xffffffffu, bv, off);
        int   oc = __shfl_down_sync(0xffffffffu, bc, off);
        if (ov > bv || (ov == bv && oc < bc)) { bv = ov; bc = oc; }
    }
    if (lane == 0) g_pred[n] = bc;
}

// INTERLEAVED mega-kernel for iteration i: odd blocks = neighborhood stats
// (f1/f2 from pred(i) + int64 LN partials into g_lnacc[par]); even blocks =
// raw SpMM gather (agg[n] = sum feat(i)[src]) into the opposite buffer.
// 256 thr, warp-per-node, parity interleave for co-residency (R16 proven).
__global__ void k_mega(int par) {
    __shared__ int hist[8][CC];
    __shared__ float4 red[8];
    int tid = threadIdx.x, wp = tid >> 5, lane = tid & 31;
    int grp = blockIdx.x >> 1;
    int n = grp * 8 + wp;

    if (blockIdx.x & 1) {
        // ---- stats ----
        hist[wp][lane] = 0; hist[wp][lane + 32] = 0;
        __syncwarp();
        int pd = g_pred[n];
        int rs = g_rowstart[n], re = g_rowstart[n + 1];
        int eq = 0;
        for (int idx = rs + lane; idx < re; idx += 32) {
            int ps = g_pred[g_csr[idx]];
            eq += (ps == pd);
            atomicAdd(&hist[wp][ps], 1);
        }
        __syncwarp();
        #pragma unroll
        for (int off = 16; off; off >>= 1) eq += __shfl_down_sync(0xffffffffu, eq, off);
        float inv = g_invdeg[n];
        float p0 = fmaxf((float)hist[wp][lane] * inv, 1e-5f);
        float p1 = fmaxf((float)hist[wp][lane + 32] * inv, 1e-5f);
        float ent = -(p0 * logf(p0) + p1 * logf(p1));
        #pragma unroll
        for (int off = 16; off; off >>= 1) ent += __shfl_down_sync(0xffffffffu, ent, off);
        if (lane == 0) {
            float f1 = (float)eq * inv;
            g_f1[n] = f1; g_f2[n] = ent;
            red[wp] = make_float4(f1, f1 * f1, ent, ent * ent);
        }
        __syncthreads();
        if (tid < 4) {
            float s = 0.0f;
            #pragma unroll
            for (int ww = 0; ww < 8; ww++) s += ((const float*)&red[ww])[tid];
            s64 q = __double2ll_rn((double)s * LN_SCALE);
            atomicAdd((u64*)&g_lnacc[par][tid], (u64)q);
        }
    } else {
        // ---- raw gather ----
        const float* __restrict__ Fs = par ? g_featB : g_featA;
        float* __restrict__ Fa = par ? g_featA : g_featB;
        int rs = g_rowstart[n], re = g_rowstart[n + 1];
        float4 acc = make_float4(0.f, 0.f, 0.f, 0.f);
        int idx = rs;
        for (; idx + 4 <= re; idx += 4) {
            int s0 = g_csr[idx], s1 = g_csr[idx + 1], s2 = g_csr[idx + 2], s3 = g_csr[idx + 3];
            float4 v0 = __ldg((const float4*)(Fs + (size_t)s0 * HH) + lane);
            float4 v1 = __ldg((const float4*)(Fs + (size_t)s1 * HH) + lane);
            float4 v2 = __ldg((const float4*)(Fs + (size_t)s2 * HH) + lane);
            float4 v3 = __ldg((const float4*)(Fs + (size_t)s3 * HH) + lane);
            acc.x += (v0.x + v1.x) + (v2.x + v3.x);
            acc.y += (v0.y + v1.y) + (v2.y + v3.y);
            acc.z += (v0.z + v1.z) + (v2.z + v3.z);
            acc.w += (v0.w + v1.w) + (v2.w + v3.w);
        }
        for (; idx < re; idx++) {
            int s = g_csr[idx];
            float4 v = __ldg((const float4*)(Fs + (size_t)s * HH) + lane);
            acc.x += v.x; acc.y += v.y; acc.z += v.z; acc.w += v.w;
        }
        ((float4*)(Fa + (size_t)n * HH))[lane] = acc;
    }
}

// iterations i=0..K-2 (after mega(i)): FUSED combine + GEMM + argmax.
// Combine: feat(i+1) = z*nm^2*agg + nm*own (z from LN(par), one expf-pair per
// node in lanes 0-7, shfl-broadcast), written in place over agg AND staged to
// smem. GEMM: proven FFMA2 on the staged rows -> pred(i+1). Never re-reads
// feat from global. Block 0 zeroes g_lnacc[par^1] for mega(i+1).
#define WTP 130
#define GW  10
__global__ void __launch_bounds__(32 * GW) k_gemm_combine(
        int par, const float* __restrict__ w, const float* __restrict__ b,
        const float* __restrict__ tau1, const float* __restrict__ tau2) {
    __shared__ __align__(8) float ws_t[CC][WTP];           // ~32.5 KB
    __shared__ __align__(16) float4 srow[GW][8][HH / 4];   // 40 KB
    const float* __restrict__ Fown = par ? g_featB : g_featA;  // feat(i)
    float* __restrict__ Fio = par ? g_featA : g_featB;         // agg in, feat(i+1) out
    int tid = threadIdx.x;
    if (blockIdx.x == 0 && tid < 4) g_lnacc[par ^ 1][tid] = 0ll;

    for (int i = tid; i < HH * CC / 4; i += 32 * GW) {
        float4 v = ((const float4*)w)[i];
        int k = i >> 4;
        int c = (i & 15) * 4;
        ws_t[c + 0][k] = v.x; ws_t[c + 1][k] = v.y;
        ws_t[c + 2][k] = v.z; ws_t[c + 3][k] = v.w;
    }
    __syncthreads();

    int wp = tid >> 5, lane = tid & 31;
    int base = blockIdx.x * (8 * GW) + wp * 8;

    // per-node gate z: lanes 0-7 each handle one node, then broadcast
    float zl = 0.0f;
    if (lane < 8) {
        const float invN = 1.0f / (float)NN;
        float S0 = (float)g_lnacc[par][0] * LN_INVSCALE;
        float S1 = (float)g_lnacc[par][1] * LN_INVSCALE;
        float S2 = (float)g_lnacc[par][2] * LN_INVSCALE;
        float S3 = (float)g_lnacc[par][3] * LN_INVSCALE;
        float m1 = S0 * invN;
        float v1 = S1 * invN - m1 * m1;
        float m2 = S2 * invN;
        float v2 = S3 * invN - m2 * m2;
        float r1 = rsqrtf(v1 + 1e-5f);
        float r2 = rsqrtf(v2 + 1e-5f);
        int n = base + lane;
        float z1 = 1.0f / (1.0f + expf((g_f1[n] - m1) * r1 - tau1[0]));
        float z2 = 1.0f / (1.0f + expf((g_f2[n] - m2) * r2 - tau2[0]));
        zl = z1 * z2;
    }

    // combine in 2 groups of 4 (MLP=8, bounded registers)
    #pragma unroll
    for (int g = 0; g < 2; g++) {
        float4 a4[4], o4[4];
        #pragma unroll
        for (int j = 0; j < 4; j++) {
            int r = g * 4 + j;
            a4[j] = __ldg((const float4*)(Fio  + (size_t)(base + r) * HH) + lane);
            o4[j] = __ldg((const float4*)(Fown + (size_t)(base + r) * HH) + lane);
        }
        #pragma unroll
        for (int j = 0; j < 4; j++) {
            int r = g * 4 + j;
            float z  = __shfl_sync(0xffffffffu, zl, r);
            float nm = g_norm[base + r];
            float s_agg = z * nm * nm;
            float4 o;
            o.x = s_agg * a4[j].x + nm * o4[j].x;
            o.y = s_agg * a4[j].y + nm * o4[j].y;
            o.z = s_agg * a4[j].z + nm * o4[j].z;
            o.w = s_agg * a4[j].w + nm * o4[j].w;
            srow[wp][r][lane] = o;
            ((float4*)(Fio + (size_t)(base + r) * HH))[lane] = o;
        }
    }
    __syncwarp();

    u64 acc0[8], acc1[8];
    #pragma unroll
    for (int r = 0; r < 8; r++) { acc0[r] = 0ull; acc1[r] = 0ull; }

    const u64* w0p = (const u64*)&ws_t[lane][0];
    const u64* w1p = (const u64*)&ws_t[lane + 32][0];
    const float4* fr = &srow[wp][0][0];

    #pragma unroll 4
    for (int k4 = 0; k4 < HH / 4; k4++) {
        u64 wa0 = w0p[2 * k4], wa1 = w0p[2 * k4 + 1];
        u64 wb0 = w1p[2 * k4], wb1 = w1p[2 * k4 + 1];
        #pragma unroll
        for (int r = 0; r < 8; r++) {
            float4 f = fr[r * (HH / 4) + k4];
            u64 fp0 = pk(f.x, f.y);
            u64 fp1 = pk(f.z, f.w);
            acc0[r] = ffma2(fp0, wa0, acc0[r]);
            acc0[r] = ffma2(fp1, wa1, acc0[r]);
            acc1[r] = ffma2(fp0, wb0, acc1[r]);
            acc1[r] = ffma2(fp1, wb1, acc1[r]);
        }
    }

    float bias0 = b[lane], bias1 = b[lane + 32];
    #pragma unroll
    for (int r = 0; r < 8; r++) {
        float2 a0 = upk(acc0[r]);
        float2 a1 = upk(acc1[r]);
        float l0 = (a0.x + a0.y) + bias0;
        float l1 = (a1.x + a1.y) + bias1;
        float bv; int bc;
        if (l1 > l0) { bv = l1; bc = lane + 32; } else { bv = l0; bc = lane; }
        #pragma unroll
        for (int off = 16; off; off >>= 1) {
            float ov = __shfl_down_sync(0xffffffffu, bv, off);
            int   oc = __shfl_down_sync(0xffffffffu, bc, off);
            if (ov > bv || (ov == bv && oc < bc)) { bv = ov; bc = oc; }
        }
        if (lane == 0) g_pred[base + r] = bc;
    }
}

// final combine (after mega(K-1)): out = z*nm*agg + own -> dout
__global__ void k_combine_out(int par, float* __restrict__ dout,
                              const float* __restrict__ tau1, const float* __restrict__ tau2) {
    int gi = blockIdx.x * blockDim.x + threadIdx.x;
    int lane = threadIdx.x & 31;
    int n = gi >> 5;
    const float* __restrict__ Fown = par ? g_featB : g_featA;
    const float* __restrict__ Fa   = par ? g_featA : g_featB;

    float z = 0.0f;
    if (lane == 0) {
        const float invN = 1.0f / (float)NN;
        float S0 = (float)g_lnacc[par][0] * LN_INVSCALE;
        float S1 = (float)g_lnacc[par][1] * LN_INVSCALE;
        float S2 = (float)g_lnacc[par][2] * LN_INVSCALE;
        float S3 = (float)g_lnacc[par][3] * LN_INVSCALE;
        float m1 = S0 * invN;
        float v1 = S1 * invN - m1 * m1;
        float m2 = S2 * invN;
        float v2 = S3 * invN - m2 * m2;
        float r1 = rsqrtf(v1 + 1e-5f);
        float r2 = rsqrtf(v2 + 1e-5f);
        float z1 = 1.0f / (1.0f + expf((g_f1[n] - m1) * r1 - tau1[0]));
        float z2 = 1.0f / (1.0f + expf((g_f2[n] - m2) * r2 - tau2[0]));
        z = z1 * z2;
    }
    z = __shfl_sync(0xffffffffu, z, 0);

    float nm = g_norm[n];
    float s_agg = z * nm;
    float4 ag = __ldg((const float4*)Fa + gi);
    float4 ow = __ldg((const float4*)Fown + gi);
    float4 o;
    o.x = s_agg * ag.x + ow.x;
    o.y = s_agg * ag.y + ow.y;
    o.z = s_agg * ag.z + ow.z;
    o.w = s_agg * ag.w + ow.w;
    ((float4*)dout)[gi] = o;
}

// ---------------- host launcher ----------------
extern "C" void kernel_launch(void* const* d_in, const int* in_sizes, int n_in,
                              void* d_out, int out_size) {
    const float* feat   = (const float*)d_in[0];
    const float* logits = (const float*)d_in[1];
    const float* w_y    = (const float*)d_in[2];
    const float* b_y    = (const float*)d_in[3];
    const float* tau1   = (const float*)d_in[4];
    const float* tau2   = (const float*)d_in[5];
    const int*   src    = (const int*)d_in[6];
    const int*   dst    = (const int*)d_in[7];
    float* out = (float*)d_out;
    (void)in_sizes; (void)n_in; (void)out_size;

    const int NB1 = (NN + 1023) / 1024;

    k_zero<<<(NN + 255) / 256, 256>>>();
    k_deg<<<(EE + 255) / 256, 256>>>(dst);
    k_norm<<<(NN + 255) / 256, 256>>>();
    k_scan1<<<NB1, 1024>>>();
    k_scan2<<<1, 1>>>(NB1);
    k_scan3<<<(NN + 255) / 256, 256>>>();
    k_csrfill<<<(EE + 255) / 256, 256>>>(src, dst);
    k_init<<<(NN * (HH / 4) + 255) / 256, 256>>>(feat);

    const int warp_blocks = (NN * 32 + 255) / 256;
    k_argmax0<<<warp_blocks, 256>>>(logits);          // pred(0)

    for (int i = 0; i < KK; i++) {
        int par = i & 1;
        k_mega<<<2 * (NN / 8), 256>>>(par);           // gather agg(i) + stats(i)
        if (i < KK - 1)
            k_gemm_combine<<<NN / 80, 32 * GW>>>(par, w_y, b_y, tau1, tau2);
        else
            k_combine_out<<<NN * (HH / 4) / 256, 256>>>(par, out, tau1, tau2);
    }
}